// round 14
// baseline (speedup 1.0000x reference)
#include <cuda_runtime.h>
#include <math.h>

// Problem constants
#define B 2
#define C 256
#define H 64
#define Wd 64
#define CMID 64
#define CENC 100
#define HH 128
#define WW 128
#define KUP 25

typedef unsigned long long u64;

// Scratch (device globals — no allocation allowed)
__device__ __align__(16) float g_W1[B * CMID * H * Wd];    // conv1x1+bn+relu
__device__ __align__(16) float g_W2a[B * CENC * H * Wd];   // conv3x3 ic half 0 (s*a+t)
__device__ __align__(16) float g_W2b[B * CENC * H * Wd];   // conv3x3 ic half 1 (s*b)
__device__ __align__(16) float g_Wn[B * KUP * HH * WW];    // softmaxed kernels

// ---- packed f32x2 helpers (sm_100+) --------------------------------------
__device__ __forceinline__ u64 splat2(float x) {
    u64 r; asm("mov.b64 %0, {%1, %1};" : "=l"(r) : "f"(x)); return r;
}
__device__ __forceinline__ u64 fma2(u64 a, u64 b, u64 c) {
    u64 d; asm("fma.rn.f32x2 %0, %1, %2, %3;" : "=l"(d)
               : "l"(a), "l"(b), "l"(c)); return d;
}
__device__ __forceinline__ float2 unpack2(u64 v) {
    float2 f; asm("mov.b64 {%0, %1}, %2;" : "=f"(f.x), "=f"(f.y) : "l"(v));
    return f;
}

// ---------------------------------------------------------------------------
// Kernel A: 1x1 conv (256 -> 64) + BN + ReLU.
// grid = (B*H, 2 col-halves), 256 threads = 32 w-cols x 8 oc-groups of 8.
// ---------------------------------------------------------------------------
__global__ void __launch_bounds__(256) conv1x1_bn_relu(
    const float* __restrict__ X, const float* __restrict__ cw,
    const float* __restrict__ gamma, const float* __restrict__ beta,
    const float* __restrict__ mean, const float* __restrict__ var)
{
    __shared__ __align__(16) float sw[128 * 64];   // 32 KB: [c_local][m]
    const int b = blockIdx.x >> 6;
    const int h = blockIdx.x & 63;
    const int tid = threadIdx.x;
    const int wcol = (blockIdx.y << 5) + (tid & 31);
    const int mg = tid >> 5;          // 0..7, oc in [mg*8, mg*8+8)

    u64 acc[4] = {0ull, 0ull, 0ull, 0ull};

    const float* Xbase = X + (size_t)b * C * H * Wd + h * Wd + wcol;

    for (int half = 0; half < 2; ++half) {
        for (int i = tid; i < 128 * 64; i += 256) {
            int c_local = i >> 6, m = i & 63;
            sw[i] = cw[m * 256 + half * 128 + c_local];
        }
        __syncthreads();
#pragma unroll 4
        for (int c = 0; c < 128; ++c) {
            float xv = Xbase[(size_t)(half * 128 + c) * (H * Wd)];
            u64 xx = splat2(xv);
            const ulonglong2* wp =
                (const ulonglong2*)&sw[c * 64 + mg * 8];
            ulonglong2 q0 = wp[0];
            ulonglong2 q1 = wp[1];
            acc[0] = fma2(xx, q0.x, acc[0]);
            acc[1] = fma2(xx, q0.y, acc[1]);
            acc[2] = fma2(xx, q1.x, acc[2]);
            acc[3] = fma2(xx, q1.y, acc[3]);
        }
        __syncthreads();
    }

#pragma unroll
    for (int j = 0; j < 4; ++j) {
        float2 v = unpack2(acc[j]);
        int m0 = mg * 8 + 2 * j;
        float s0 = gamma[m0] * rsqrtf(var[m0] + 1e-5f);
        float s1 = gamma[m0 + 1] * rsqrtf(var[m0 + 1] + 1e-5f);
        float o0 = fmaxf(fmaf(v.x, s0, beta[m0] - mean[m0] * s0), 0.f);
        float o1 = fmaxf(fmaf(v.y, s1, beta[m0 + 1] - mean[m0 + 1] * s1), 0.f);
        g_W1[(((size_t)b * CMID + m0) * H + h) * Wd + wcol] = o0;
        g_W1[(((size_t)b * CMID + m0 + 1) * H + h) * Wd + wcol] = o1;
    }
}

// ---------------------------------------------------------------------------
// Kernel B: 3x3 conv (64 -> 100, pad=1), BN folded into the two ic-halves:
//   half 0 writes s*partial + t,   half 1 writes s*partial
// so (g_W2a + g_W2b) == full BN output. Softmax kernel sums them.
// grid = (8 tiles of 32x16, B, 10 = 5 oc-groups x 2 ic-halves), 128 threads.
// Thread: 4 pixels (rows ry,ry+4,ry+8,ry+12) x 20 oc (10 f32x2 pairs).
// Per (ic,tap): 4 LDS-x + 4 splat + 5 LDS.128-w + 40 FFMA2 = 0.66 instr/FMA.
// ---------------------------------------------------------------------------
#define ICB3 8
__global__ void __launch_bounds__(128) conv3x3_bn(
    const float* __restrict__ ew,
    const float* __restrict__ gamma, const float* __restrict__ beta,
    const float* __restrict__ mean, const float* __restrict__ var)
{
    __shared__ __align__(16) float xs[ICB3 * 18 * 34];   // 19.1 KB
    __shared__ __align__(16) float ws[ICB3 * 9 * 24];    // 6.75 KB (20 used, pad 24)

    const int tile = blockIdx.x;               // 0..7
    const int b = blockIdx.y;
    const int ocg = blockIdx.z >> 1;           // 5 groups of 20 oc
    const int ih  = blockIdx.z & 1;            // ic half
    const int tx0 = (tile & 1) * 32, ty0 = (tile >> 1) * 16;
    const int tid = threadIdx.x;
    const int px = tid & 31, ry = tid >> 5;    // rows ry+4m, m=0..3

    u64 acc[4][10];
#pragma unroll
    for (int m = 0; m < 4; ++m)
#pragma unroll
        for (int j = 0; j < 10; ++j) acc[m][j] = 0ull;

    for (int ib = 0; ib < 4; ++ib) {
        const int icb = ih * 32 + ib * ICB3;
        for (int i = tid; i < ICB3 * 612; i += 128) {
            int ic = i / 612, pos = i % 612;
            int r = pos / 34, c = pos % 34;
            int gr = ty0 + r - 1, gc = tx0 + c - 1;
            float v = 0.f;
            if ((unsigned)gr < 64u && (unsigned)gc < 64u)
                v = g_W1[(((size_t)b * CMID + icb + ic) * H + gr) * Wd + gc];
            xs[i] = v;
        }
        for (int i = tid; i < ICB3 * 180; i += 128) {
            int ic = i / 180, rem = i % 180;
            int tap = rem / 20, l = rem % 20;
            ws[(ic * 9 + tap) * 24 + l] =
                ew[((size_t)(ocg * 20 + l) * CMID + icb + ic) * 9 + tap];
        }
        __syncthreads();
#pragma unroll 1
        for (int ic = 0; ic < ICB3; ++ic) {
#pragma unroll
            for (int ky = 0; ky < 3; ++ky)
#pragma unroll
            for (int kx = 0; kx < 3; ++kx) {
                u64 xx[4];
#pragma unroll
                for (int m = 0; m < 4; ++m)
                    xx[m] = splat2(
                        xs[ic * 612 + (ry + 4 * m + ky) * 34 + (px + kx)]);
                const ulonglong2* wrow =
                    (const ulonglong2*)&ws[(ic * 9 + ky * 3 + kx) * 24];
#pragma unroll
                for (int q = 0; q < 5; ++q) {
                    ulonglong2 wq = wrow[q];
#pragma unroll
                    for (int m = 0; m < 4; ++m) {
                        acc[m][2 * q] = fma2(xx[m], wq.x, acc[m][2 * q]);
                        acc[m][2 * q + 1] = fma2(xx[m], wq.y, acc[m][2 * q + 1]);
                    }
                }
            }
        }
        __syncthreads();
    }

    float* dst = ih ? g_W2b : g_W2a;
    const int w = tx0 + px;
#pragma unroll
    for (int j = 0; j < 10; ++j) {
        int oc = ocg * 20 + 2 * j;
        float s0 = gamma[oc] * rsqrtf(var[oc] + 1e-5f);
        float s1 = gamma[oc + 1] * rsqrtf(var[oc + 1] + 1e-5f);
        float t0 = ih ? 0.f : (beta[oc] - mean[oc] * s0);
        float t1 = ih ? 0.f : (beta[oc + 1] - mean[oc + 1] * s1);
#pragma unroll
        for (int m = 0; m < 4; ++m) {
            float2 v = unpack2(acc[m][j]);
            int h = ty0 + ry + 4 * m;
            dst[(((size_t)b * CENC + oc) * H + h) * Wd + w] = fmaf(v.x, s0, t0);
            dst[(((size_t)b * CENC + oc + 1) * H + h) * Wd + w] =
                fmaf(v.y, s1, t1);
        }
    }
}

// ---------------------------------------------------------------------------
// Kernel C: sum halves + pixel_shuffle(r=2) + clamp + pow + softmax (25 taps).
// ---------------------------------------------------------------------------
__global__ void __launch_bounds__(256) shuffle_pow_softmax(
    const float* __restrict__ power_p)
{
    const int idx = blockIdx.x * 256 + threadIdx.x;   // 0 .. 32767
    const int b = idx >> 14;
    const int pix = idx & 16383;
    const int y = pix >> 7, x = pix & 127;
    const int yi = y >> 1, xi = x & 127 ? (x >> 1) : 0;
    const int xi2 = x >> 1;
    const int off = (y & 1) * 2 + (x & 1);
    (void)xi;

    const float p = fmaxf(power_p[0], 1e-5f);

    float v[25];
    float mx = -1e30f;
#pragma unroll
    for (int k = 0; k < 25; ++k) {
        size_t o = (((size_t)b * CENC + k * 4 + off) * H + yi) * Wd + xi2;
        float w = g_W2a[o] + g_W2b[o];
        w = fmaxf(w, 1e-5f);
        w = __powf(w, p);
        v[k] = w;
        mx = fmaxf(mx, w);
    }
    float s = 0.f;
#pragma unroll
    for (int k = 0; k < 25; ++k) { v[k] = __expf(v[k] - mx); s += v[k]; }
    float inv = 1.f / s;
#pragma unroll
    for (int k = 0; k < 25; ++k)
        g_Wn[(((size_t)b * KUP + k) * HH + y) * WW + x] = v[k] * inv;
}

// ---------------------------------------------------------------------------
// Kernel D: CARAFE aggregate on the low-res grid.
// out[b,c,2yi+sy,2xi+sx] = sum_{ki,kj} W * X[b,c,yi+ki-2,xi+kj-2]
// Thread owns ONE subpixel (sy,sx) of one low-res pixel; its 25 scalar
// weights are pre-splatted into u64 regs at setup. The X tile lives in smem
// as channel-pair-packed float2, so the inner body is exactly
//   LDS.64 (2 channels) + FFMA2 (weight-splat reg)  — no movs, no splats.
// LDS.64 lane stride 8 B -> conflict-free. Two 32-ch phases per block.
// grid = (64 tiles of 2x32, 4 ch-groups of 64, B), 256 threads.
// ---------------------------------------------------------------------------
__global__ void __launch_bounds__(256) carafe_agg(
    const float* __restrict__ X, float* __restrict__ out)
{
    __shared__ __align__(16) float2 xs[16 * 216];  // 16 ch-pairs x 6r x 36c = 27.6 KB
    const int b = blockIdx.z;
    const int cg = blockIdx.y;                 // channels [cg*64, cg*64+64)
    const int tile = blockIdx.x;
    const int ty0 = (tile >> 1) * 2, tx0 = (tile & 1) * 32;
    const int tid = threadIdx.x;
    const int pxi = tid & 31;
    const int pyi = (tid >> 5) & 1;
    const int sy = (tid >> 6) & 1;
    const int sx = tid >> 7;
    const int yi = ty0 + pyi, xi = tx0 + pxi;
    const int yo = 2 * yi + sy, xo = 2 * xi + sx;

    // 25 pre-splatted weights for this thread's subpixel.
    u64 wk[25];
#pragma unroll
    for (int k = 0; k < 25; ++k)
        wk[k] = splat2(g_Wn[(((size_t)b * KUP + k) * HH + yo) * WW + xo]);

    const size_t cbase = (size_t)b * C + cg * 64;

    for (int h2 = 0; h2 < 2; ++h2) {
        __syncthreads();
        // Fill channel-pair-packed tile: 16 pairs x 6 rows x 36 cols, halo 2.
        for (int i = tid; i < 16 * 216; i += 256) {
            int cp = i / 216, pos = i % 216;
            int r = pos / 36, c = pos % 36;
            int gr = ty0 + r - 2, gc = tx0 + c - 2;
            float v0 = 0.f, v1 = 0.f;
            if ((unsigned)gr < 64u && (unsigned)gc < 64u) {
                const float* xp =
                    X + ((cbase + h2 * 32 + cp * 2) * H + gr) * Wd + gc;
                v0 = xp[0];
                v1 = xp[H * Wd];
            }
            xs[i] = make_float2(v0, v1);
        }
        __syncthreads();

#pragma unroll 1
        for (int j = 0; j < 8; ++j) {
            const u64* p0 = (const u64*)&xs[(2 * j) * 216 + pyi * 36 + pxi];
            const u64* p1 = (const u64*)&xs[(2 * j + 1) * 216 + pyi * 36 + pxi];
            u64 a0 = 0ull, a1 = 0ull;
#pragma unroll
            for (int ki = 0; ki < 5; ++ki)
#pragma unroll
            for (int kj = 0; kj < 5; ++kj) {
                const int k = ki * 5 + kj;
                a0 = fma2(p0[ki * 36 + kj], wk[k], a0);
                a1 = fma2(p1[ki * 36 + kj], wk[k], a1);
            }
            float2 v0 = unpack2(a0), v1 = unpack2(a1);
            float* op = out + ((cbase + h2 * 32 + 4 * j) * HH + yo) * WW + xo;
            op[0] = v0.x;
            op[(size_t)HH * WW] = v0.y;
            op[2 * (size_t)HH * WW] = v1.x;
            op[3 * (size_t)HH * WW] = v1.y;
        }
    }
}

// ---------------------------------------------------------------------------
extern "C" void kernel_launch(void* const* d_in, const int* in_sizes, int n_in,
                              void* d_out, int out_size) {
    const float* X          = (const float*)d_in[0];
    const float* comp_w     = (const float*)d_in[1];
    const float* comp_gamma = (const float*)d_in[2];
    const float* comp_beta  = (const float*)d_in[3];
    const float* comp_mean  = (const float*)d_in[4];
    const float* comp_var   = (const float*)d_in[5];
    const float* enc_w      = (const float*)d_in[6];
    const float* enc_gamma  = (const float*)d_in[7];
    const float* enc_beta   = (const float*)d_in[8];
    const float* enc_mean   = (const float*)d_in[9];
    const float* enc_var    = (const float*)d_in[10];
    const float* power_p    = (const float*)d_in[11];
    float* out = (float*)d_out;

    conv1x1_bn_relu<<<dim3(B * H, 2), 256>>>(X, comp_w, comp_gamma, comp_beta,
                                             comp_mean, comp_var);
    conv3x3_bn<<<dim3(8, B, 10), 128>>>(enc_w, enc_gamma, enc_beta,
                                        enc_mean, enc_var);
    shuffle_pow_softmax<<<(B * HH * WW) / 256, 256>>>(power_p);
    carafe_agg<<<dim3(64, 4, B), 256>>>(X, out);
}

// round 17
// speedup vs baseline: 1.1883x; 1.1883x over previous
#include <cuda_runtime.h>
#include <math.h>

// Problem constants
#define B 2
#define C 256
#define H 64
#define Wd 64
#define CMID 64
#define CENC 100
#define HH 128
#define WW 128
#define KUP 25
#define QS (B * CENC * H * Wd)   // one conv3x3 partial buffer

typedef unsigned long long u64;

// Scratch (device globals — no allocation allowed)
__device__ __align__(16) float g_W1[B * CMID * H * Wd];  // conv1x1+bn+relu
__device__ __align__(16) float g_W2q[4 * QS];            // conv3x3 raw ic-quarters
__device__ __align__(16) float g_Wn[B * KUP * HH * WW];  // softmaxed kernels

// ---- packed f32x2 helpers (sm_100+) --------------------------------------
__device__ __forceinline__ u64 splat2(float x) {
    u64 r; asm("mov.b64 %0, {%1, %1};" : "=l"(r) : "f"(x)); return r;
}
__device__ __forceinline__ u64 fma2(u64 a, u64 b, u64 c) {
    u64 d; asm("fma.rn.f32x2 %0, %1, %2, %3;" : "=l"(d)
               : "l"(a), "l"(b), "l"(c)); return d;
}
__device__ __forceinline__ float2 unpack2(u64 v) {
    float2 f; asm("mov.b64 {%0, %1}, %2;" : "=f"(f.x), "=f"(f.y) : "l"(v));
    return f;
}

// ---------------------------------------------------------------------------
// Kernel A: 1x1 conv (256 -> 64) + BN + ReLU.
// grid = (B*H, 2 col-halves), 256 threads = 32 w-cols x 8 oc-groups of 8.
// ---------------------------------------------------------------------------
__global__ void __launch_bounds__(256) conv1x1_bn_relu(
    const float* __restrict__ X, const float* __restrict__ cw,
    const float* __restrict__ gamma, const float* __restrict__ beta,
    const float* __restrict__ mean, const float* __restrict__ var)
{
    __shared__ __align__(16) float sw[128 * 64];   // 32 KB: [c_local][m]
    const int b = blockIdx.x >> 6;
    const int h = blockIdx.x & 63;
    const int tid = threadIdx.x;
    const int wcol = (blockIdx.y << 5) + (tid & 31);
    const int mg = tid >> 5;          // 0..7, oc in [mg*8, mg*8+8)

    u64 acc[4] = {0ull, 0ull, 0ull, 0ull};

    const float* Xbase = X + (size_t)b * C * H * Wd + h * Wd + wcol;

    for (int half = 0; half < 2; ++half) {
        for (int i = tid; i < 128 * 64; i += 256) {
            int c_local = i >> 6, m = i & 63;
            sw[i] = cw[m * 256 + half * 128 + c_local];
        }
        __syncthreads();
#pragma unroll 4
        for (int c = 0; c < 128; ++c) {
            float xv = Xbase[(size_t)(half * 128 + c) * (H * Wd)];
            u64 xx = splat2(xv);
            const ulonglong2* wp =
                (const ulonglong2*)&sw[c * 64 + mg * 8];
            ulonglong2 q0 = wp[0];
            ulonglong2 q1 = wp[1];
            acc[0] = fma2(xx, q0.x, acc[0]);
            acc[1] = fma2(xx, q0.y, acc[1]);
            acc[2] = fma2(xx, q1.x, acc[2]);
            acc[3] = fma2(xx, q1.y, acc[3]);
        }
        __syncthreads();
    }

#pragma unroll
    for (int j = 0; j < 4; ++j) {
        float2 v = unpack2(acc[j]);
        int m0 = mg * 8 + 2 * j;
        float s0 = gamma[m0] * rsqrtf(var[m0] + 1e-5f);
        float s1 = gamma[m0 + 1] * rsqrtf(var[m0 + 1] + 1e-5f);
        float o0 = fmaxf(fmaf(v.x, s0, beta[m0] - mean[m0] * s0), 0.f);
        float o1 = fmaxf(fmaf(v.y, s1, beta[m0 + 1] - mean[m0 + 1] * s1), 0.f);
        g_W1[(((size_t)b * CMID + m0) * H + h) * Wd + wcol] = o0;
        g_W1[(((size_t)b * CMID + m0 + 1) * H + h) * Wd + wcol] = o1;
    }
}

// ---------------------------------------------------------------------------
// Kernel B: 3x3 conv (64 -> 100, pad=1), RAW partial sums (no BN here).
// ic split into 4 quarters of 16; quarter q writes g_W2q + q*QS.
// BN affine is applied in the softmax kernel to the summed partials.
// grid = (16 tiles of 16x16, B, 20 = 5 oc-groups x 4 ic-quarters),
// 64 threads = 16 px x 4 ry; each thread does 4 rows (ry+4m) x 20 oc.
// Weight smem loads are warp-uniform broadcasts -> kernel is fma-bound.
// ---------------------------------------------------------------------------
__global__ void __launch_bounds__(64) conv3x3_q(const float* __restrict__ ew)
{
    __shared__ float xs[8 * 324];                       // 10.4 KB
    __shared__ __align__(16) float ws[8 * 9 * 24];      // 6.9 KB (20 used, pad 24)

    const int tile = blockIdx.x;               // 16 tiles of 16x16
    const int b = blockIdx.y;
    const int ocg = blockIdx.z >> 2;           // 0..4  (20 oc each)
    const int icq = blockIdx.z & 3;            // 0..3  (16 ic each)
    const int ty0 = (tile >> 2) * 16, tx0 = (tile & 3) * 16;
    const int tid = threadIdx.x;
    const int px = tid & 15, ry = tid >> 4;    // rows ry + 4m, m = 0..3

    u64 acc[4][10];
#pragma unroll
    for (int m = 0; m < 4; ++m)
#pragma unroll
        for (int j = 0; j < 10; ++j) acc[m][j] = 0ull;

    for (int ib = 0; ib < 2; ++ib) {
        const int icb = icq * 16 + ib * 8;
        for (int i = tid; i < 8 * 324; i += 64) {
            int ic = i / 324, pos = i % 324;
            int r = pos / 18, c = pos % 18;
            int gr = ty0 + r - 1, gc = tx0 + c - 1;
            float v = 0.f;
            if ((unsigned)gr < 64u && (unsigned)gc < 64u)
                v = g_W1[(((size_t)b * CMID + icb + ic) * H + gr) * Wd + gc];
            xs[i] = v;
        }
        for (int i = tid; i < 8 * 180; i += 64) {
            int ic = i / 180, rem = i % 180;
            int tap = rem / 20, l = rem % 20;
            ws[(ic * 9 + tap) * 24 + l] =
                ew[((size_t)(ocg * 20 + l) * CMID + icb + ic) * 9 + tap];
        }
        __syncthreads();
#pragma unroll 1
        for (int ic = 0; ic < 8; ++ic) {
#pragma unroll
            for (int ky = 0; ky < 3; ++ky)
#pragma unroll
            for (int kx = 0; kx < 3; ++kx) {
                u64 xx[4];
#pragma unroll
                for (int m = 0; m < 4; ++m)
                    xx[m] = splat2(
                        xs[ic * 324 + (ry + 4 * m + ky) * 18 + (px + kx)]);
                const ulonglong2* wrow =
                    (const ulonglong2*)&ws[(ic * 9 + ky * 3 + kx) * 24];
#pragma unroll
                for (int q = 0; q < 5; ++q) {
                    ulonglong2 wq = wrow[q];
#pragma unroll
                    for (int m = 0; m < 4; ++m) {
                        acc[m][2 * q] = fma2(xx[m], wq.x, acc[m][2 * q]);
                        acc[m][2 * q + 1] = fma2(xx[m], wq.y, acc[m][2 * q + 1]);
                    }
                }
            }
        }
        __syncthreads();
    }

    float* dst = g_W2q + (size_t)icq * QS;
    const int w = tx0 + px;
#pragma unroll
    for (int j = 0; j < 10; ++j) {
        int oc = ocg * 20 + 2 * j;
#pragma unroll
        for (int m = 0; m < 4; ++m) {
            float2 v = unpack2(acc[m][j]);
            int h = ty0 + ry + 4 * m;
            dst[(((size_t)b * CENC + oc) * H + h) * Wd + w] = v.x;
            dst[(((size_t)b * CENC + oc + 1) * H + h) * Wd + w] = v.y;
        }
    }
}

// ---------------------------------------------------------------------------
// Kernel C: sum 4 partials + BN affine + pixel_shuffle(2) + clamp + pow +
// softmax over 25 taps. BN scale/shift precomputed into smem per block.
// ---------------------------------------------------------------------------
__global__ void __launch_bounds__(256) shuffle_pow_softmax(
    const float* __restrict__ power_p,
    const float* __restrict__ gamma, const float* __restrict__ beta,
    const float* __restrict__ mean, const float* __restrict__ var)
{
    __shared__ float ss[100], st[100];
    if (threadIdx.x < 100) {
        float s = gamma[threadIdx.x] * rsqrtf(var[threadIdx.x] + 1e-5f);
        ss[threadIdx.x] = s;
        st[threadIdx.x] = beta[threadIdx.x] - mean[threadIdx.x] * s;
    }
    __syncthreads();

    const int idx = blockIdx.x * 256 + threadIdx.x;   // 0 .. 32767
    const int b = idx >> 14;
    const int pix = idx & 16383;
    const int y = pix >> 7, x = pix & 127;
    const int yi = y >> 1, xi = x >> 1;
    const int off = (y & 1) * 2 + (x & 1);

    const float p = fmaxf(power_p[0], 1e-5f);

    float v[25];
    float mx = -1e30f;
#pragma unroll
    for (int k = 0; k < 25; ++k) {
        int oc = k * 4 + off;
        size_t o = (((size_t)b * CENC + oc) * H + yi) * Wd + xi;
        float w = (g_W2q[o] + g_W2q[o + QS]) +
                  (g_W2q[o + 2 * (size_t)QS] + g_W2q[o + 3 * (size_t)QS]);
        w = fmaf(w, ss[oc], st[oc]);
        w = fmaxf(w, 1e-5f);
        w = __powf(w, p);
        v[k] = w;
        mx = fmaxf(mx, w);
    }
    float s = 0.f;
#pragma unroll
    for (int k = 0; k < 25; ++k) { v[k] = __expf(v[k] - mx); s += v[k]; }
    float inv = 1.f / s;
#pragma unroll
    for (int k = 0; k < 25; ++k)
        g_Wn[(((size_t)b * KUP + k) * HH + y) * WW + x] = v[k] * inv;
}

// ---------------------------------------------------------------------------
// Kernel D: CARAFE aggregate on the low-res grid.
// out[b,c,2yi+sy,2xi+sx] = sum_{ki,kj} W * X[b,c,yi+ki-2,xi+kj-2]
// A thread owns one FULL low-res quad (all 4 subpixels share the exact same
// 25 X taps) and a 32-channel slice. Accumulator f32x2 lanes = sx, so the
// quad's weights load directly as u64 pairs from g_Wn (w01 = row 2yi,
// w23 = row 2yi+1; 50 u64 regs, loaded once). X tile is channel-pair-packed
// float2 in smem; per (ch-pair, tap): 1 LDS.64 + 2 splat movs + 4 FFMA2
// = 7 instr / 8 FMA, 1 B/FMA crossbar.
// grid = (64 tiles of 2x32, 4 ch-groups of 64, B), 128 threads
//      = 64 quads x 2 ch-lanes; two 32-channel smem phases.
// ---------------------------------------------------------------------------
__global__ void __launch_bounds__(128, 3) carafe_agg(
    const float* __restrict__ X, float* __restrict__ out)
{
    __shared__ __align__(16) float2 xs[16 * 216];  // 16 ch-pairs x 6r x 36c
    const int b = blockIdx.z;
    const int cg = blockIdx.y;                 // channels [cg*64, cg*64+64)
    const int tile = blockIdx.x;
    const int ty0 = (tile >> 1) * 2, tx0 = (tile & 1) * 32;
    const int tid = threadIdx.x;
    const int pxi = tid & 31;
    const int pyi = (tid >> 5) & 1;
    const int lane = tid >> 6;                 // 0..1 (channel halves)
    const int yi = ty0 + pyi, xi = tx0 + pxi;
    const int yo = 2 * yi, xo = 2 * xi;

    // This quad's weights: u64 pairs over sx, rows yo (w01) and yo+1 (w23).
    u64 w01[25], w23[25];
#pragma unroll
    for (int k = 0; k < 25; ++k) {
        const float* p = g_Wn + (((size_t)b * KUP + k) * HH + yo) * WW + xo;
        w01[k] = *(const u64*)p;
        w23[k] = *(const u64*)(p + WW);
    }

    const size_t cbase = (size_t)b * C + cg * 64;

    for (int h2 = 0; h2 < 2; ++h2) {
        __syncthreads();
        // Channel-pair-packed tile: 16 pairs x 6 rows x 36 cols, halo 2.
        for (int i = tid; i < 16 * 216; i += 128) {
            int cp = i / 216, pos = i % 216;
            int r = pos / 36, c = pos % 36;
            int gr = ty0 + r - 2, gc = tx0 + c - 2;
            float v0 = 0.f, v1 = 0.f;
            if ((unsigned)gr < 64u && (unsigned)gc < 64u) {
                const float* xp =
                    X + ((cbase + h2 * 32 + cp * 2) * H + gr) * Wd + gc;
                v0 = xp[0];
                v1 = xp[H * Wd];
            }
            xs[i] = make_float2(v0, v1);
        }
        __syncthreads();

#pragma unroll 1
        for (int j = 0; j < 8; ++j) {
            const int cp = lane * 8 + j;
            const float2* xp = &xs[cp * 216 + pyi * 36 + pxi];
            u64 a00 = 0ull, a01 = 0ull, a10 = 0ull, a11 = 0ull; // [ch][sy]
#pragma unroll
            for (int ki = 0; ki < 5; ++ki)
#pragma unroll
            for (int kj = 0; kj < 5; ++kj) {
                const int k = ki * 5 + kj;
                float2 xv = xp[ki * 36 + kj];
                u64 s0 = splat2(xv.x);
                u64 s1 = splat2(xv.y);
                a00 = fma2(s0, w01[k], a00);
                a01 = fma2(s0, w23[k], a01);
                a10 = fma2(s1, w01[k], a10);
                a11 = fma2(s1, w23[k], a11);
            }
            const size_t c0 = cbase + h2 * 32 + cp * 2;
            float* op = out + (c0 * HH + yo) * WW + xo;
            *(u64*)op = a00;
            *(u64*)(op + WW) = a01;
            *(u64*)(op + (size_t)HH * WW) = a10;
            *(u64*)(op + (size_t)HH * WW + WW) = a11;
        }
    }
}

// ---------------------------------------------------------------------------
extern "C" void kernel_launch(void* const* d_in, const int* in_sizes, int n_in,
                              void* d_out, int out_size) {
    const float* X          = (const float*)d_in[0];
    const float* comp_w     = (const float*)d_in[1];
    const float* comp_gamma = (const float*)d_in[2];
    const float* comp_beta  = (const float*)d_in[3];
    const float* comp_mean  = (const float*)d_in[4];
    const float* comp_var   = (const float*)d_in[5];
    const float* enc_w      = (const float*)d_in[6];
    const float* enc_gamma  = (const float*)d_in[7];
    const float* enc_beta   = (const float*)d_in[8];
    const float* enc_mean   = (const float*)d_in[9];
    const float* enc_var    = (const float*)d_in[10];
    const float* power_p    = (const float*)d_in[11];
    float* out = (float*)d_out;

    conv1x1_bn_relu<<<dim3(B * H, 2), 256>>>(X, comp_w, comp_gamma, comp_beta,
                                             comp_mean, comp_var);
    conv3x3_q<<<dim3(16, B, 20), 64>>>(enc_w);
    shuffle_pow_softmax<<<(B * HH * WW) / 256, 256>>>(
        power_p, enc_gamma, enc_beta, enc_mean, enc_var);
    carafe_agg<<<dim3(64, 4, B), 128>>>(X, out);
}